// round 5
// baseline (speedup 1.0000x reference)
#include <cuda_runtime.h>
#include <cuda_bf16.h>
#include <cstdint>

#define DIM 1024
#define NGROUPS 32
#define GSIZE 32
#define TT 1024
#define BB 16
#define MROWS (TT * BB)          // 16384
#define BD (BB * DIM)            // 16384

// ---------------- scratch (device globals; no allocation allowed) ----------------
__device__ float g_vx[MROWS * DIM];
__device__ float g_alpha[MROWS * DIM];
__device__ float g_delta[MROWS * DIM];
__device__ float g_compete[MROWS * DIM];

// ---------------- helpers ----------------
__device__ __forceinline__ uint32_t f2tf32(float x) {
    uint32_t r;
    asm("cvt.rna.tf32.f32 %0, %1;" : "=r"(r) : "f"(x));
    return r;
}

__device__ __forceinline__ void mma_tf32(float* c, const uint32_t* a, const uint32_t* b) {
    asm volatile(
        "mma.sync.aligned.m16n8k8.row.col.f32.tf32.tf32.f32 "
        "{%0,%1,%2,%3}, {%4,%5,%6,%7}, {%8,%9}, {%0,%1,%2,%3};"
        : "+f"(c[0]), "+f"(c[1]), "+f"(c[2]), "+f"(c[3])
        : "r"(a[0]), "r"(a[1]), "r"(a[2]), "r"(a[3]), "r"(b[0]), "r"(b[1]));
}

__device__ __forceinline__ void ldsm_x4(uint32_t& r0, uint32_t& r1, uint32_t& r2, uint32_t& r3,
                                        uint32_t addr) {
    asm volatile("ldmatrix.sync.aligned.m8n8.x4.shared.b16 {%0,%1,%2,%3}, [%4];"
                 : "=r"(r0), "=r"(r1), "=r"(r2), "=r"(r3) : "r"(addr));
}

__device__ __forceinline__ uint32_t smem_u32(const void* p) {
    uint32_t a;
    asm("{ .reg .u64 t; cvta.to.shared.u64 t, %1; cvt.u32.u64 %0, t; }" : "=r"(a) : "l"(p));
    return a;
}

// ---------------- GEMM: C[M,N] = A[M,K] @ W[N,K]^T ----------------
// Block tile 256x128, 8 warps, warp tile 64x64. Double-buffered smem, ldmatrix feeds.
// fused=1: blockIdx.x in [0,24): wsel = x>>3 selects (W,bias,C,mode 0/1/2)
//   mode 0: y = acc + bias;  1: y = 1+softplus(acc+bias);  2: y = sigmoid(acc+bias)
// fused=0: mode 3: y = compete * silu(acc)
#define BM 256
#define BN 128
#define BK 16
#define LDW 20                       // smem row stride in words (80B)
#define A_ROWSZ (LDW * 4)            // 80 bytes
#define A_BUF_BYTES (BM * A_ROWSZ)   // 20480
#define B_BUF_BYTES (BN * A_ROWSZ)   // 10240
#define SM_B_OFF (2 * A_BUF_BYTES)   // 40960
#define SMEM_GEMM (2 * A_BUF_BYTES + 2 * B_BUF_BYTES)   // 61440

__global__ void __launch_bounds__(256)
gemm_tf32_kernel(const float* __restrict__ A,
                 const float* __restrict__ W0, const float* __restrict__ W1,
                 const float* __restrict__ W2,
                 const float* __restrict__ bias0, const float* __restrict__ bias1,
                 const float* __restrict__ bias2,
                 const float* __restrict__ comp,
                 float* __restrict__ C0, float* __restrict__ C1, float* __restrict__ C2,
                 int fused)
{
    extern __shared__ char smem[];
    uint32_t* Asw = (uint32_t*)smem;                       // [2][BM][LDW]
    uint32_t* Bsw = (uint32_t*)(smem + SM_B_OFF);          // [2][BN][LDW]

    const int K = DIM, N = DIM;

    int mode, ntile;
    const float* W;
    const float* bias;
    float* C;
    if (fused) {
        int wsel = blockIdx.x >> 3;
        ntile = blockIdx.x & 7;
        mode = wsel;
        W    = (wsel == 0) ? W0 : ((wsel == 1) ? W1 : W2);
        bias = (wsel == 0) ? bias0 : ((wsel == 1) ? bias1 : bias2);
        C    = (wsel == 0) ? C0 : ((wsel == 1) ? C1 : C2);
    } else {
        mode = 3; ntile = blockIdx.x; W = W0; bias = bias0; C = C0;
    }

    const int tid  = threadIdx.x;
    const int lane = tid & 31;
    const int warp = tid >> 5;
    const int warpM = warp >> 1;   // 0..3
    const int warpN = warp & 1;    // 0..1
    const int wmBase = warpM * 64;
    const int wnBase = warpN * 64;

    const int m0 = blockIdx.y * BM;
    const int n0 = ntile * BN;

    // staging mapping (R3-proven): row = tid>>2 (0..63), col chunk = (tid&3)*4
    const int ldRow = tid >> 2;
    const int ldCol = (tid & 3) * 4;

    const float* Aptr = A + (size_t)(m0 + ldRow) * K + ldCol;   // + p*64*K, p=0..3
    const float* Wptr = W + (size_t)(n0 + ldRow) * K + ldCol;   // + p*64*K, p=0..1

    // ldmatrix per-thread source row/col within a 16x8 tf32 tile
    const int lRow = (lane & 7) + ((lane >> 3) & 1) * 8;  // 0..15
    const int lK   = (lane >> 4) * 4;                     // 0 or 4

    const uint32_t sb = smem_u32(smem);
    // hoisted LDSM base addresses (buffer 0)
    uint32_t aBase = sb + (uint32_t)(wmBase + lRow) * A_ROWSZ + (uint32_t)lK * 4;
    uint32_t bBase = sb + SM_B_OFF + (uint32_t)(wnBase + lRow) * A_ROWSZ + (uint32_t)lK * 4;

    float acc[4][8][4];
#pragma unroll
    for (int i = 0; i < 4; i++)
#pragma unroll
        for (int j = 0; j < 8; j++)
#pragma unroll
            for (int r = 0; r < 4; r++) acc[i][j][r] = 0.f;

    const int grp = lane >> 2;   // 0..7
    const int tig = lane & 3;    // 0..3

    float4 va[4], vb[2];

    // ---- prologue: stage k0=0 into buffer 0 ----
#pragma unroll
    for (int p = 0; p < 4; p++) va[p] = *(const float4*)(Aptr + (size_t)(p * 64) * K);
#pragma unroll
    for (int p = 0; p < 2; p++) vb[p] = *(const float4*)(Wptr + (size_t)(p * 64) * K);
    {
#pragma unroll
        for (int p = 0; p < 4; p++) {
            uint32_t* dst = Asw + (size_t)(ldRow + p * 64) * LDW + ldCol;
            dst[0] = f2tf32(va[p].x); dst[1] = f2tf32(va[p].y);
            dst[2] = f2tf32(va[p].z); dst[3] = f2tf32(va[p].w);
        }
#pragma unroll
        for (int p = 0; p < 2; p++) {
            uint32_t* dst = Bsw + (size_t)(ldRow + p * 64) * LDW + ldCol;
            dst[0] = f2tf32(vb[p].x); dst[1] = f2tf32(vb[p].y);
            dst[2] = f2tf32(vb[p].z); dst[3] = f2tf32(vb[p].w);
        }
    }
    __syncthreads();

    uint32_t bufOffA = 0, bufOffB = 0;   // byte offsets of current buffer
#pragma unroll 1
    for (int k0 = 0; k0 < K; k0 += BK) {
        const bool has_next = (k0 + BK) < K;
        if (has_next) {
            int kn = k0 + BK;
#pragma unroll
            for (int p = 0; p < 4; p++) va[p] = *(const float4*)(Aptr + (size_t)(p * 64) * K + kn);
#pragma unroll
            for (int p = 0; p < 2; p++) vb[p] = *(const float4*)(Wptr + (size_t)(p * 64) * K + kn);
        }

        // ---- compute on current buffer via ldmatrix ----
        const uint32_t aB = aBase + bufOffA;
        const uint32_t bB = bBase + bufOffB;
#pragma unroll
        for (int kk = 0; kk < BK; kk += 8) {
            const uint32_t kOff = (uint32_t)kk * 4;
            uint32_t af[4][4];
#pragma unroll
            for (int mt = 0; mt < 4; mt++)
                ldsm_x4(af[mt][0], af[mt][1], af[mt][2], af[mt][3],
                        aB + (uint32_t)(mt * 16) * A_ROWSZ + kOff);
            uint32_t bf[8][2];
#pragma unroll
            for (int pr = 0; pr < 4; pr++)
                ldsm_x4(bf[2 * pr][0], bf[2 * pr + 1][0], bf[2 * pr][1], bf[2 * pr + 1][1],
                        bB + (uint32_t)(pr * 16) * A_ROWSZ + kOff);
#pragma unroll
            for (int mt = 0; mt < 4; mt++)
#pragma unroll
                for (int nt = 0; nt < 8; nt++)
                    mma_tf32(acc[mt][nt], af[mt], bf[nt]);
        }

        if (has_next) {
            const uint32_t nA = bufOffA ^ A_BUF_BYTES;
            const uint32_t nB = bufOffB ^ B_BUF_BYTES;
            uint32_t* AsN = (uint32_t*)(smem + nA);
            uint32_t* BsN = (uint32_t*)(smem + SM_B_OFF + nB);
#pragma unroll
            for (int p = 0; p < 4; p++) {
                uint32_t* dst = AsN + (size_t)(ldRow + p * 64) * LDW + ldCol;
                dst[0] = f2tf32(va[p].x); dst[1] = f2tf32(va[p].y);
                dst[2] = f2tf32(va[p].z); dst[3] = f2tf32(va[p].w);
            }
#pragma unroll
            for (int p = 0; p < 2; p++) {
                uint32_t* dst = BsN + (size_t)(ldRow + p * 64) * LDW + ldCol;
                dst[0] = f2tf32(vb[p].x); dst[1] = f2tf32(vb[p].y);
                dst[2] = f2tf32(vb[p].z); dst[3] = f2tf32(vb[p].w);
            }
            bufOffA = nA; bufOffB = nB;
        }
        __syncthreads();
    }

    // ---- epilogue (float2 stores: reg pairs are adjacent columns) ----
#pragma unroll
    for (int mt = 0; mt < 4; mt++) {
#pragma unroll
        for (int nt = 0; nt < 8; nt++) {
#pragma unroll
            for (int half = 0; half < 2; half++) {
                int row = m0 + wmBase + mt * 16 + grp + half * 8;
                int col = n0 + wnBase + nt * 8 + 2 * tig;
                float v0 = acc[mt][nt][half * 2 + 0];
                float v1 = acc[mt][nt][half * 2 + 1];
                float y0, y1;
                if (mode == 0) {
                    y0 = v0 + bias[col]; y1 = v1 + bias[col + 1];
                } else if (mode == 1) {
                    float x0 = v0 + bias[col], x1 = v1 + bias[col + 1];
                    y0 = 1.0f + ((x0 > 20.f) ? x0 : log1pf(__expf(x0)));
                    y1 = 1.0f + ((x1 > 20.f) ? x1 : log1pf(__expf(x1)));
                } else if (mode == 2) {
                    float x0 = v0 + bias[col], x1 = v1 + bias[col + 1];
                    y0 = 1.0f / (1.0f + __expf(-x0));
                    y1 = 1.0f / (1.0f + __expf(-x1));
                } else {
                    float s0 = v0 / (1.0f + __expf(-v0));
                    float s1 = v1 / (1.0f + __expf(-v1));
                    const float2 cc = *(const float2*)(comp + (size_t)row * N + col);
                    y0 = cc.x * s0; y1 = cc.y * s1;
                }
                float2 o; o.x = y0; o.y = y1;
                *(float2*)(C + (size_t)row * N + col) = o;
            }
        }
    }
}

// ---------------- sequential scan: batched prefetch ahead of the dependency chain ----
__global__ void __launch_bounds__(128)
scan_kernel(const float* __restrict__ vx, const float* __restrict__ alpha,
            const float* __restrict__ delta, const float* __restrict__ h0,
            const float* __restrict__ r_h, float* __restrict__ out_h)
{
    int gtid = blockIdx.x * 128 + threadIdx.x;   // 0..16383
    int b = gtid >> 10;
    int d = gtid & 1023;
    size_t base = (size_t)b * DIM + d;

    float rh = r_h[d];
    float h = h0[base];
    out_h[base] = h;

    float cv[8], ca[8], cd[8], nv[8], na[8], nd[8];
#pragma unroll
    for (int i = 0; i < 8; i++) {
        size_t o = (size_t)i * BD + base;
        cv[i] = __ldcs(vx + o); ca[i] = __ldcs(alpha + o); cd[i] = __ldcs(delta + o);
    }

    for (int t0 = 0; t0 < TT; t0 += 8) {
        const bool more = (t0 + 8) < TT;
        if (more) {
#pragma unroll
            for (int i = 0; i < 8; i++) {
                size_t o = (size_t)(t0 + 8 + i) * BD + base;
                nv[i] = __ldcs(vx + o); na[i] = __ldcs(alpha + o); nd[i] = __ldcs(delta + o);
            }
        }
#pragma unroll
        for (int i = 0; i < 8; i++) {
            float v = cv[i] + rh * h;
            float av = fminf(fmaxf(fabsf(v), 1e-6f), 10.0f);
            float cand = __powf(av, ca[i]);
            cand = (v >= 0.f) ? cand : -cand;
            if (v == 0.f) cand = 0.f;
            h = h + cd[i] * (cand - h);
            __stcs(out_h + (size_t)(t0 + i + 1) * BD + base, h);
        }
        if (more) {
#pragma unroll
            for (int i = 0; i < 8; i++) { cv[i] = nv[i]; ca[i] = na[i]; cd[i] = nd[i]; }
        }
    }
}

// ---------------- compete = group softmax over h[1:], fully parallel ----------------
__global__ void __launch_bounds__(256)
compete_kernel(const float* __restrict__ h, float* __restrict__ comp)
{
    size_t idx = (size_t)blockIdx.x * blockDim.x + threadIdx.x;
    float v = h[idx];
    float m = v;
#pragma unroll
    for (int o = 16; o > 0; o >>= 1) m = fmaxf(m, __shfl_xor_sync(0xffffffffu, m, o));
    float e = __expf(v - m);
    float s = e;
#pragma unroll
    for (int o = 16; o > 0; o >>= 1) s += __shfl_xor_sync(0xffffffffu, s, o);
    comp[idx] = e / s;
}

// ---------------- launch ----------------
extern "C" void kernel_launch(void* const* d_in, const int* in_sizes, int n_in,
                              void* d_out, int out_size)
{
    const float* x       = (const float*)d_in[0];
    const float* h0      = (const float*)d_in[1];
    const float* W_x     = (const float*)d_in[2];
    const float* r_h     = (const float*)d_in[3];
    const float* b       = (const float*)d_in[4];
    const float* W_alpha = (const float*)d_in[5];
    const float* b_alpha = (const float*)d_in[6];
    const float* W_delta = (const float*)d_in[7];
    const float* b_delta = (const float*)d_in[8];
    const float* W_out   = (const float*)d_in[9];

    float* out = (float*)d_out;
    float* out_h = out;                                  // [T+1,B,D]
    float* out_y = out + (size_t)(TT + 1) * BD;          // [T,B,D]

    float *vx, *al, *dl, *cp;
    cudaGetSymbolAddress((void**)&vx, g_vx);
    cudaGetSymbolAddress((void**)&al, g_alpha);
    cudaGetSymbolAddress((void**)&dl, g_delta);
    cudaGetSymbolAddress((void**)&cp, g_compete);

    cudaFuncSetAttribute(gemm_tf32_kernel, cudaFuncAttributeMaxDynamicSharedMemorySize,
                         SMEM_GEMM);

    // 1) fused projections: one launch, 3 weights (A tile L2-shared across weights)
    dim3 pgrid(3 * (DIM / BN), MROWS / BM);   // (24, 64)
    gemm_tf32_kernel<<<pgrid, 256, SMEM_GEMM>>>(x, W_x, W_alpha, W_delta,
                                                b, b_alpha, b_delta,
                                                nullptr, vx, al, dl, 1);
    // 2) sequential scan -> h states (written straight into d_out)
    scan_kernel<<<128, 128>>>(vx, al, dl, h0, r_h, out_h);
    // 3) group softmax over h[1:]
    compete_kernel<<<(MROWS * DIM) / 256, 256>>>(out_h + BD, cp);
    // 4) output GEMM with compete*silu epilogue
    dim3 ogrid(DIM / BN, MROWS / BM);          // (8, 64)
    gemm_tf32_kernel<<<ogrid, 256, SMEM_GEMM>>>(out_h + BD, W_out, nullptr, nullptr,
                                                nullptr, nullptr, nullptr,
                                                cp, out_y, nullptr, nullptr, 0);
}